// round 15
// baseline (speedup 1.0000x reference)
#include <cuda_runtime.h>
#include <math.h>
#include <stdint.h>

#define NX 160
#define D  48
#define NW 3
#define N3 (NX*NX*NX)
#define M_TV 159
#define ZS_STRIDE 162   // row stride for zs[r][c]: even (LDS.64 align), mod 32 = 2 (low conflict)

// Scratch (device globals: allocation-free per harness rules)
__device__ float g_G2[NW*NX*NX*D];    // [w][a][b][r]
__device__ float4 g_G3[(size_t)N3];   // [n] = {g[w=0], g[w=1], g[w=2], 0}
__device__ double g_tv;
__device__ unsigned int g_cnt;        // TV completion counter (reset by last block)

// ---- L2 cache-policy helpers (createpolicy + cache_hint form) ----
__device__ __forceinline__ uint64_t pol_evict_last() {
    uint64_t p;
    asm("createpolicy.fractional.L2::evict_last.b64 %0, 1.0;" : "=l"(p));
    return p;
}
__device__ __forceinline__ uint64_t pol_evict_first() {
    uint64_t p;
    asm("createpolicy.fractional.L2::evict_first.b64 %0, 1.0;" : "=l"(p));
    return p;
}
__device__ __forceinline__ float ldg_f32_pol(const float* p, uint64_t pol) {
    float v;
    asm("ld.global.nc.L2::cache_hint.f32 %0, [%1], %2;"
        : "=f"(v) : "l"(p), "l"(pol));
    return v;
}
__device__ __forceinline__ float4 ldg_f4_pol(const float4* p, uint64_t pol) {
    float4 v;
    asm("ld.global.nc.L2::cache_hint.v4.f32 {%0,%1,%2,%3}, [%4], %5;"
        : "=f"(v.x), "=f"(v.y), "=f"(v.z), "=f"(v.w) : "l"(p), "l"(pol));
    return v;
}
__device__ __forceinline__ int4 ldg_i4_pol(const int4* p, uint64_t pol) {
    int4 v;
    asm("ld.global.nc.L2::cache_hint.v4.s32 {%0,%1,%2,%3}, [%4], %5;"
        : "=r"(v.x), "=r"(v.y), "=r"(v.z), "=r"(v.w) : "l"(p), "l"(pol));
    return v;
}
__device__ __forceinline__ void stg_f4_pol(float4* p, float4 v, uint64_t pol) {
    asm volatile("st.global.L2::cache_hint.v4.f32 [%0], {%1,%2,%3,%4}, %5;"
        :: "l"(p), "f"(v.x), "f"(v.y), "f"(v.z), "f"(v.w), "l"(pol) : "memory");
}
__device__ __forceinline__ void stg_f32_cs(float* p, float v) {
    asm volatile("st.global.cs.f32 [%0], %1;" :: "l"(p), "f"(v) : "memory");
}

// K12 (fused k1+k2): block (w,a).
//  Phase A: G1tile[q][r] = sum_p x[a,p] * W[w,p,q,r]  -> smem
//  Phase B: G2[w][a][b][r] = sum_q y[b,q] * G1tile[q][r] -> global
__global__ void k12(const float* __restrict__ x, const float* __restrict__ y,
                    const float* __restrict__ W) {
    int blk = blockIdx.x;
    int w = blk / NX, a = blk % NX;
    __shared__ float ys[NX][D];     // 30.72 KB
    __shared__ float g1s[D][D];     // 9.22 KB
    __shared__ float xs[D];
    int t = threadIdx.x;
    if (blk == 0 && t == 0) g_tv = 0.0;
    if (t < D) xs[t] = x[a*D + t];
    for (int i = t; i < NX*D; i += 256) ys[i/D][i%D] = y[i];
    __syncthreads();

    const float* Wp = W + (size_t)w*D*D*D;  // [p][q*48+r]
    {
        float acc[9];
        #pragma unroll
        for (int j = 0; j < 9; j++) acc[j] = 0.f;
        for (int p = 0; p < D; p++) {
            float xv = xs[p];
            const float* row = Wp + p*(D*D);
            #pragma unroll
            for (int j = 0; j < 9; j++) acc[j] = fmaf(xv, row[t + 256*j], acc[j]);
        }
        #pragma unroll
        for (int j = 0; j < 9; j++) {
            int idx = t + 256*j;
            g1s[idx / D][idx % D] = acc[j];
        }
    }
    __syncthreads();

    int tx = t & 15, ty = t >> 4;
    float acc[10][3];
    #pragma unroll
    for (int jb = 0; jb < 10; jb++)
        #pragma unroll
        for (int jr = 0; jr < 3; jr++) acc[jb][jr] = 0.f;
    for (int q = 0; q < D; q++) {
        float yv[10], gv[3];
        #pragma unroll
        for (int jb = 0; jb < 10; jb++) yv[jb] = ys[ty + 16*jb][q];
        #pragma unroll
        for (int jr = 0; jr < 3; jr++) gv[jr] = g1s[q][tx + 16*jr];
        #pragma unroll
        for (int jb = 0; jb < 10; jb++)
            #pragma unroll
            for (int jr = 0; jr < 3; jr++)
                acc[jb][jr] = fmaf(yv[jb], gv[jr], acc[jb][jr]);
    }
    float* outp = g_G2 + (size_t)blk*NX*D;
    #pragma unroll
    for (int jb = 0; jb < 10; jb++)
        #pragma unroll
        for (int jr = 0; jr < 3; jr++)
            outp[(ty + 16*jb)*D + tx + 16*jr] = acc[jb][jr];
}

// K3: g[w,a,b,c] = sum_r G2[w][a][b][r] * z[c,r]  -> g_G3[n] = {w0,w1,w2,0}
// R11 version (best measured): packed fp32x2 FMA, 1 b-row x 5 c-pairs x 3 w,
// occ 4, STG.128 stores tagged evict_last.
__global__ void __launch_bounds__(256, 4) k3(const float* __restrict__ z) {
    int blk = blockIdx.x;
    int a = blk / 10, bt = blk % 10;
    __shared__ float zs[D * ZS_STRIDE];       // [r][c], 31.1 KB
    __shared__ float g2s[NW][16][D];          // 9.2 KB
    int t = threadIdx.x;
    for (int i = t; i < NX*D; i += 256) {
        int c = i / D, r = i % D;
        zs[r*ZS_STRIDE + c] = z[i];
    }
    for (int i = t; i < NW*16*D; i += 256) {
        int w = i / (16*D);
        int rem = i % (16*D);
        int bl = rem / D, r = rem % D;
        g2s[w][bl][r] = g_G2[(((size_t)w*NX + a)*NX + bt*16 + bl)*D + r];
    }
    __syncthreads();
    int tx = t & 15, ty = t >> 4;

    unsigned long long acc[NW][5];
    #pragma unroll
    for (int w = 0; w < NW; w++)
        #pragma unroll
        for (int jc = 0; jc < 5; jc++) acc[w][jc] = 0ULL;

    int c_base = 2*tx;
    #pragma unroll 4
    for (int r = 0; r < D; r++) {
        unsigned long long wp[NW];
        #pragma unroll
        for (int w = 0; w < NW; w++) {
            unsigned int gb = __float_as_uint(g2s[w][ty][r]);
            asm("mov.b64 %0, {%1, %1};" : "=l"(wp[w]) : "r"(gb));
        }
        const float* zrow = &zs[r*ZS_STRIDE];
        #pragma unroll
        for (int jc = 0; jc < 5; jc++) {
            unsigned long long zp =
                *reinterpret_cast<const unsigned long long*>(&zrow[c_base + 32*jc]);
            #pragma unroll
            for (int w = 0; w < NW; w++)
                asm("fma.rn.f32x2 %0, %1, %2, %0;" : "+l"(acc[w][jc]) : "l"(zp), "l"(wp[w]));
        }
    }

    uint64_t pev = pol_evict_last();
    int b = bt*16 + ty;
    size_t rowbase = ((size_t)a*NX + b)*NX;
    #pragma unroll
    for (int jc = 0; jc < 5; jc++) {
        int c0 = c_base + 32*jc;
        unsigned int lo[NW], hi[NW];
        #pragma unroll
        for (int w = 0; w < NW; w++)
            asm("mov.b64 {%0, %1}, %2;" : "=r"(lo[w]), "=r"(hi[w]) : "l"(acc[w][jc]));
        float4 f0, f1;
        f0.x = __uint_as_float(lo[0]); f0.y = __uint_as_float(lo[1]);
        f0.z = __uint_as_float(lo[2]); f0.w = 0.f;
        f1.x = __uint_as_float(hi[0]); f1.y = __uint_as_float(hi[1]);
        f1.z = __uint_as_float(hi[2]); f1.w = 0.f;
        stg_f4_pol(&g_G3[rowbase + c0],     f0, pev);
        stg_f4_pol(&g_G3[rowbase + c0 + 1], f1, pev);
    }
}

// Merged TV + gather kernel. Blocks [0, TVB) do TV; the rest gather.
// Both only READ g_G3 -> safe concurrency. TV result written by the LAST
// TV block (completion counter), which also resets the counter for graph replay.
#define B_RUN 4
#define NBQ   ((M_TV + B_RUN - 1) / B_RUN)   // 40
#define TV_N   (M_TV*NBQ*NX)                 // TV thread count
#define TVB    ((TV_N + 255)/256)            // 3975 TV blocks

__global__ void __launch_bounds__(256) k_tvgather(
        const int* __restrict__ B_idx, const float* __restrict__ B_w,
        float* __restrict__ out, int NP, int tv_pos) {
    int blk = blockIdx.x;
    int t = threadIdx.x;

    if (blk < TVB) {
        // ---- TV path ----
        int idx = blk*256 + t;
        float val = 0.f;
        if (idx < TV_N) {
            int c = idx % NX;
            int tmp = idx / NX;
            int bq = tmp % NBQ;
            int a = tmp / NBQ;
            if (c < M_TV) {
                uint64_t pev = pol_evict_last();
                int b0 = bq * B_RUN;
                size_t n = ((size_t)a*NX + b0)*NX + c;
                float4 v0 = ldg_f4_pol(&g_G3[n], pev);
                #pragma unroll
                for (int j = 0; j < B_RUN; j++) {
                    if (b0 + j >= M_TV) break;
                    float4 vb = ldg_f4_pol(&g_G3[n + NX], pev);
                    float4 vc = ldg_f4_pol(&g_G3[n + 1], pev);
                    float4 va = ldg_f4_pol(&g_G3[n + (size_t)NX*NX], pev);
                    float dc, db, da;
                    dc = vc.x - v0.x; db = vb.x - v0.x; da = va.x - v0.x;
                    val += sqrtf(1e-5f + dc*dc + db*db + da*da);
                    dc = vc.y - v0.y; db = vb.y - v0.y; da = va.y - v0.y;
                    val += sqrtf(1e-5f + dc*dc + db*db + da*da);
                    dc = vc.z - v0.z; db = vb.z - v0.z; da = va.z - v0.z;
                    val += sqrtf(1e-5f + dc*dc + db*db + da*da);
                    v0 = vb;
                    n += NX;
                }
            }
        }
        #pragma unroll
        for (int o = 16; o > 0; o >>= 1) val += __shfl_down_sync(0xffffffffu, val, o);
        __shared__ float warp_sums[8];
        if ((t & 31) == 0) warp_sums[t >> 5] = val;
        __syncthreads();
        if (t == 0) {
            float s = 0.f;
            #pragma unroll
            for (int i = 0; i < 8; i++) s += warp_sums[i];
            atomicAdd(&g_tv, (double)s);
            __threadfence();
            unsigned int prev = atomicAdd(&g_cnt, 1u);
            if (prev == TVB - 1) {
                // all TV blocks' g_tv adds are visible (fence + atomic chain)
                __threadfence();
                double denom = (double)M_TV * M_TV * M_TV;
                out[tv_pos] = (float)(g_tv / denom);  // SCALING = 1.0
                g_cnt = 0;  // reset for next graph replay
            }
        }
        return;
    }

    // ---- gather path ----
    long long tid = (long long)(blk - TVB)*256 + t;
    int i  = (int)(tid >> 2);
    int lw = (int)(tid & 3);
    if (i >= NP) return;
    uint64_t pef = pol_evict_first();
    uint64_t pev = pol_evict_last();
    int4   i0 = ldg_i4_pol((const int4*)(B_idx + (size_t)i*8),     pef);
    int4   i1 = ldg_i4_pol((const int4*)(B_idx + (size_t)i*8) + 1, pef);
    float4 w0 = ldg_f4_pol((const float4*)(B_w + (size_t)i*8),     pef);
    float4 w1 = ldg_f4_pol((const float4*)(B_w + (size_t)i*8) + 1, pef);
    int   idxs[8] = {i0.x, i0.y, i0.z, i0.w, i1.x, i1.y, i1.z, i1.w};
    float ws[8]   = {w0.x, w0.y, w0.z, w0.w, w1.x, w1.y, w1.z, w1.w};
    const float* G3f = (const float*)g_G3;
    float v[8];
    #pragma unroll
    for (int k = 0; k < 8; k++)
        v[k] = ldg_f32_pol(G3f + (((size_t)idxs[k]) << 2) + lw, pev);
    float acc = 0.f;
    #pragma unroll
    for (int k = 0; k < 8; k++) acc = fmaf(ws[k], v[k], acc);
    if (lw < 3) stg_f32_cs(out + (size_t)i*3 + lw, acc);
}

extern "C" void kernel_launch(void* const* d_in, const int* in_sizes, int n_in,
                              void* d_out, int out_size) {
    const float* x  = (const float*)d_in[0];
    const float* y  = (const float*)d_in[1];
    const float* z  = (const float*)d_in[2];
    const float* W  = (const float*)d_in[3];
    const int*   Bi = (const int*)d_in[4];
    const float* Bw = (const float*)d_in[5];
    float* out = (float*)d_out;
    int NP = in_sizes[4] / 8;

    k12<<<NW*NX, 256>>>(x, y, W);
    k3<<<NX*10, 256>>>(z);
    long long gthreads = (long long)NP * 4;
    int gblocks = (int)((gthreads + 255)/256);
    k_tvgather<<<TVB + gblocks, 256>>>(Bi, Bw, out, NP, out_size - 1);
}

// round 17
// speedup vs baseline: 1.0285x; 1.0285x over previous
#include <cuda_runtime.h>
#include <math.h>
#include <stdint.h>

#define NX 160
#define D  48
#define NW 3
#define N3 (NX*NX*NX)
#define M_TV 159
#define ZS_STRIDE 162   // row stride for zs[r][c]: even (LDS.64 align), mod 32 = 2 (low conflict)

// Scratch (device globals: allocation-free per harness rules)
__device__ float g_G2[NW*NX*NX*D];    // [w][a][b][r]
__device__ float4 g_G3[(size_t)N3];   // [n] = {g[w=0], g[w=1], g[w=2], 0}
__device__ double g_tv;
__device__ unsigned int g_cnt;        // TV completion counter (reset by last block)

// ---- L2 cache-policy helpers (createpolicy + cache_hint form) ----
__device__ __forceinline__ uint64_t pol_evict_last() {
    uint64_t p;
    asm("createpolicy.fractional.L2::evict_last.b64 %0, 1.0;" : "=l"(p));
    return p;
}
__device__ __forceinline__ uint64_t pol_evict_first() {
    uint64_t p;
    asm("createpolicy.fractional.L2::evict_first.b64 %0, 1.0;" : "=l"(p));
    return p;
}
__device__ __forceinline__ float ldg_f32_pol(const float* p, uint64_t pol) {
    float v;
    asm("ld.global.nc.L2::cache_hint.f32 %0, [%1], %2;"
        : "=f"(v) : "l"(p), "l"(pol));
    return v;
}
__device__ __forceinline__ float4 ldg_f4_pol(const float4* p, uint64_t pol) {
    float4 v;
    asm("ld.global.nc.L2::cache_hint.v4.f32 {%0,%1,%2,%3}, [%4], %5;"
        : "=f"(v.x), "=f"(v.y), "=f"(v.z), "=f"(v.w) : "l"(p), "l"(pol));
    return v;
}
__device__ __forceinline__ int4 ldg_i4_pol(const int4* p, uint64_t pol) {
    int4 v;
    asm("ld.global.nc.L2::cache_hint.v4.s32 {%0,%1,%2,%3}, [%4], %5;"
        : "=r"(v.x), "=r"(v.y), "=r"(v.z), "=r"(v.w) : "l"(p), "l"(pol));
    return v;
}
__device__ __forceinline__ void stg_f4_pol(float4* p, float4 v, uint64_t pol) {
    asm volatile("st.global.L2::cache_hint.v4.f32 [%0], {%1,%2,%3,%4}, %5;"
        :: "l"(p), "f"(v.x), "f"(v.y), "f"(v.z), "f"(v.w), "l"(pol) : "memory");
}
__device__ __forceinline__ void stg_f32_cs(float* p, float v) {
    asm volatile("st.global.cs.f32 [%0], %1;" :: "l"(p), "f"(v) : "memory");
}

// K12 (fused k1+k2): block (w,a).
//  Phase A: G1tile[q][r] = sum_p x[a,p] * W[w,p,q,r]  -> smem
//           (4-deep load batching: 36 LDGs in flight to hide L2-hit latency)
//  Phase B: G2[w][a][b][r] = sum_q y[b,q] * G1tile[q][r] -> global
//           (f32x2 packed along r-pairs: 8x32 thread layout, 15 FFMA2/q)
__global__ void __launch_bounds__(256) k12(
        const float* __restrict__ x, const float* __restrict__ y,
        const float* __restrict__ W) {
    int blk = blockIdx.x;
    int w = blk / NX, a = blk % NX;
    __shared__ float ys[NX][D];     // 30.72 KB
    __shared__ float g1s[D][D];     // 9.22 KB  [q][r]
    __shared__ float xs[D];
    int t = threadIdx.x;
    if (blk == 0 && t == 0) g_tv = 0.0;
    if (t < D) xs[t] = x[a*D + t];
    for (int i = t; i < NX*D; i += 256) ys[i/D][i%D] = y[i];
    __syncthreads();

    // Phase A: 9 contiguous qr entries per thread; p batched by 4.
    const float* Wp = W + (size_t)w*D*D*D;  // [p][q*48+r]
    {
        float acc[9];
        #pragma unroll
        for (int j = 0; j < 9; j++) acc[j] = 0.f;
        for (int p0 = 0; p0 < D; p0 += 4) {
            float wv[4][9];
            #pragma unroll
            for (int d = 0; d < 4; d++) {
                const float* row = Wp + (p0 + d)*(D*D);
                #pragma unroll
                for (int j = 0; j < 9; j++) wv[d][j] = __ldg(row + t + 256*j);
            }
            #pragma unroll
            for (int d = 0; d < 4; d++) {
                float xv = xs[p0 + d];
                #pragma unroll
                for (int j = 0; j < 9; j++) acc[j] = fmaf(xv, wv[d][j], acc[j]);
            }
        }
        #pragma unroll
        for (int j = 0; j < 9; j++) {
            int idx = t + 256*j;
            g1s[idx / D][idx % D] = acc[j];
        }
    }
    __syncthreads();

    // Phase B: thread (tx<8, ty<32); r-pairs rp = tx + 8*jr (jr<3), b = ty + 32*jb (jb<5)
    int tx = t & 7, ty = t >> 3;
    unsigned long long acc2[5][3];
    #pragma unroll
    for (int jb = 0; jb < 5; jb++)
        #pragma unroll
        for (int jr = 0; jr < 3; jr++) acc2[jb][jr] = 0ULL;
    for (int q = 0; q < D; q++) {
        unsigned long long gp[3];
        #pragma unroll
        for (int jr = 0; jr < 3; jr++)
            gp[jr] = *reinterpret_cast<const unsigned long long*>(&g1s[q][2*(tx + 8*jr)]);
        #pragma unroll
        for (int jb = 0; jb < 5; jb++) {
            unsigned long long yp;
            unsigned int yb = __float_as_uint(ys[ty + 32*jb][q]);
            asm("mov.b64 %0, {%1, %1};" : "=l"(yp) : "r"(yb));
            #pragma unroll
            for (int jr = 0; jr < 3; jr++)
                asm("fma.rn.f32x2 %0, %1, %2, %0;" : "+l"(acc2[jb][jr]) : "l"(gp[jr]), "l"(yp));
        }
    }
    float* outp = g_G2 + (size_t)blk*NX*D;
    #pragma unroll
    for (int jb = 0; jb < 5; jb++) {
        int b = ty + 32*jb;
        #pragma unroll
        for (int jr = 0; jr < 3; jr++)
            *reinterpret_cast<unsigned long long*>(&outp[b*D + 2*(tx + 8*jr)]) = acc2[jb][jr];
    }
}

// K3: g[w,a,b,c] = sum_r G2[w][a][b][r] * z[c,r]  -> g_G3[n] = {w0,w1,w2,0}
// R11 version (best measured): packed fp32x2 FMA, 1 b-row x 5 c-pairs x 3 w,
// occ 4, STG.128 stores tagged evict_last.
__global__ void __launch_bounds__(256, 4) k3(const float* __restrict__ z) {
    int blk = blockIdx.x;
    int a = blk / 10, bt = blk % 10;
    __shared__ float zs[D * ZS_STRIDE];       // [r][c], 31.1 KB
    __shared__ float g2s[NW][16][D];          // 9.2 KB
    int t = threadIdx.x;
    for (int i = t; i < NX*D; i += 256) {
        int c = i / D, r = i % D;
        zs[r*ZS_STRIDE + c] = z[i];
    }
    for (int i = t; i < NW*16*D; i += 256) {
        int w = i / (16*D);
        int rem = i % (16*D);
        int bl = rem / D, r = rem % D;
        g2s[w][bl][r] = g_G2[(((size_t)w*NX + a)*NX + bt*16 + bl)*D + r];
    }
    __syncthreads();
    int tx = t & 15, ty = t >> 4;

    unsigned long long acc[NW][5];
    #pragma unroll
    for (int w = 0; w < NW; w++)
        #pragma unroll
        for (int jc = 0; jc < 5; jc++) acc[w][jc] = 0ULL;

    int c_base = 2*tx;
    #pragma unroll 4
    for (int r = 0; r < D; r++) {
        unsigned long long wp[NW];
        #pragma unroll
        for (int w = 0; w < NW; w++) {
            unsigned int gb = __float_as_uint(g2s[w][ty][r]);
            asm("mov.b64 %0, {%1, %1};" : "=l"(wp[w]) : "r"(gb));
        }
        const float* zrow = &zs[r*ZS_STRIDE];
        #pragma unroll
        for (int jc = 0; jc < 5; jc++) {
            unsigned long long zp =
                *reinterpret_cast<const unsigned long long*>(&zrow[c_base + 32*jc]);
            #pragma unroll
            for (int w = 0; w < NW; w++)
                asm("fma.rn.f32x2 %0, %1, %2, %0;" : "+l"(acc[w][jc]) : "l"(zp), "l"(wp[w]));
        }
    }

    uint64_t pev = pol_evict_last();
    int b = bt*16 + ty;
    size_t rowbase = ((size_t)a*NX + b)*NX;
    #pragma unroll
    for (int jc = 0; jc < 5; jc++) {
        int c0 = c_base + 32*jc;
        unsigned int lo[NW], hi[NW];
        #pragma unroll
        for (int w = 0; w < NW; w++)
            asm("mov.b64 {%0, %1}, %2;" : "=r"(lo[w]), "=r"(hi[w]) : "l"(acc[w][jc]));
        float4 f0, f1;
        f0.x = __uint_as_float(lo[0]); f0.y = __uint_as_float(lo[1]);
        f0.z = __uint_as_float(lo[2]); f0.w = 0.f;
        f1.x = __uint_as_float(hi[0]); f1.y = __uint_as_float(hi[1]);
        f1.z = __uint_as_float(hi[2]); f1.w = 0.f;
        stg_f4_pol(&g_G3[rowbase + c0],     f0, pev);
        stg_f4_pol(&g_G3[rowbase + c0 + 1], f1, pev);
    }
}

// Merged TV + gather with 1-in-8 block interleave: TV work spread through the
// gather wave so its FMA/sqrt fills gather's idle issue slots.
// TV block  <=> (blk & 7) == 7 && (blk >> 3) < TVB,  tv_blk = blk >> 3.
// Gather block: g_blk = blk - min(blk >> 3 + 1, TVB-adjusted count below blk).
#define B_RUN 4
#define NBQ   ((M_TV + B_RUN - 1) / B_RUN)   // 40
#define TV_N   (M_TV*NBQ*NX)                 // TV thread count
#define TVB    ((TV_N + 255)/256)            // 3975 TV blocks

__global__ void __launch_bounds__(256) k_tvgather(
        const int* __restrict__ B_idx, const float* __restrict__ B_w,
        float* __restrict__ out, int NP, int tv_pos) {
    int blk = blockIdx.x;
    int t = threadIdx.x;

    if (((blk & 7) == 7) && ((blk >> 3) < TVB)) {
        // ---- TV path ----
        int idx = (blk >> 3)*256 + t;
        float val = 0.f;
        if (idx < TV_N) {
            int c = idx % NX;
            int tmp = idx / NX;
            int bq = tmp % NBQ;
            int a = tmp / NBQ;
            if (c < M_TV) {
                uint64_t pev = pol_evict_last();
                int b0 = bq * B_RUN;
                size_t n = ((size_t)a*NX + b0)*NX + c;
                float4 v0 = ldg_f4_pol(&g_G3[n], pev);
                #pragma unroll
                for (int j = 0; j < B_RUN; j++) {
                    if (b0 + j >= M_TV) break;
                    float4 vb = ldg_f4_pol(&g_G3[n + NX], pev);
                    float4 vc = ldg_f4_pol(&g_G3[n + 1], pev);
                    float4 va = ldg_f4_pol(&g_G3[n + (size_t)NX*NX], pev);
                    float dc, db, da;
                    dc = vc.x - v0.x; db = vb.x - v0.x; da = va.x - v0.x;
                    val += sqrtf(1e-5f + dc*dc + db*db + da*da);
                    dc = vc.y - v0.y; db = vb.y - v0.y; da = va.y - v0.y;
                    val += sqrtf(1e-5f + dc*dc + db*db + da*da);
                    dc = vc.z - v0.z; db = vb.z - v0.z; da = va.z - v0.z;
                    val += sqrtf(1e-5f + dc*dc + db*db + da*da);
                    v0 = vb;
                    n += NX;
                }
            }
        }
        #pragma unroll
        for (int o = 16; o > 0; o >>= 1) val += __shfl_down_sync(0xffffffffu, val, o);
        __shared__ float warp_sums[8];
        if ((t & 31) == 0) warp_sums[t >> 5] = val;
        __syncthreads();
        if (t == 0) {
            float s = 0.f;
            #pragma unroll
            for (int i = 0; i < 8; i++) s += warp_sums[i];
            atomicAdd(&g_tv, (double)s);
            __threadfence();
            unsigned int prev = atomicAdd(&g_cnt, 1u);
            if (prev == TVB - 1) {
                __threadfence();
                double denom = (double)M_TV * M_TV * M_TV;
                out[tv_pos] = (float)(g_tv / denom);  // SCALING = 1.0
                g_cnt = 0;  // reset for next graph replay
            }
        }
        return;
    }

    // ---- gather path ----
    int tvcnt = blk >> 3;             // # TV blocks strictly below blk
    if (tvcnt > TVB) tvcnt = TVB;
    long long tid = (long long)(blk - tvcnt)*256 + t;
    int i  = (int)(tid >> 2);
    int lw = (int)(tid & 3);
    if (i >= NP) return;
    uint64_t pef = pol_evict_first();
    uint64_t pev = pol_evict_last();
    int4   i0 = ldg_i4_pol((const int4*)(B_idx + (size_t)i*8),     pef);
    int4   i1 = ldg_i4_pol((const int4*)(B_idx + (size_t)i*8) + 1, pef);
    float4 w0 = ldg_f4_pol((const float4*)(B_w + (size_t)i*8),     pef);
    float4 w1 = ldg_f4_pol((const float4*)(B_w + (size_t)i*8) + 1, pef);
    int   idxs[8] = {i0.x, i0.y, i0.z, i0.w, i1.x, i1.y, i1.z, i1.w};
    float ws[8]   = {w0.x, w0.y, w0.z, w0.w, w1.x, w1.y, w1.z, w1.w};
    const float* G3f = (const float*)g_G3;
    float v[8];
    #pragma unroll
    for (int k = 0; k < 8; k++)
        v[k] = ldg_f32_pol(G3f + (((size_t)idxs[k]) << 2) + lw, pev);
    float acc = 0.f;
    #pragma unroll
    for (int k = 0; k < 8; k++) acc = fmaf(ws[k], v[k], acc);
    if (lw < 3) stg_f32_cs(out + (size_t)i*3 + lw, acc);
}

extern "C" void kernel_launch(void* const* d_in, const int* in_sizes, int n_in,
                              void* d_out, int out_size) {
    const float* x  = (const float*)d_in[0];
    const float* y  = (const float*)d_in[1];
    const float* z  = (const float*)d_in[2];
    const float* W  = (const float*)d_in[3];
    const int*   Bi = (const int*)d_in[4];
    const float* Bw = (const float*)d_in[5];
    float* out = (float*)d_out;
    int NP = in_sizes[4] / 8;

    k12<<<NW*NX, 256>>>(x, y, W);
    k3<<<NX*10, 256>>>(z);
    long long gthreads = (long long)NP * 4;
    int gblocks = (int)((gthreads + 255)/256);   // 31250
    // total blocks: gather blocks + interleaved TV blocks (1 in 8)
    k_tvgather<<<gblocks + TVB, 256>>>(Bi, Bw, out, NP, out_size - 1);
}